// round 12
// baseline (speedup 1.0000x reference)
#include <cuda_runtime.h>
#include <math.h>
#include <stdint.h>

#define SEQ   4096
#define INDIM 64
#define D     1024
#define G     4096      // 4*D
#define NCTA  148
#define RTHR  512
#define NCHUNK (NCTA * 3)   // 444 LL packets (3 per CTA, some partial/inactive)

typedef unsigned long long u64;

// ---------------- scratch (device globals: allocation-free) ----------------
__device__ float g_x [(size_t)SEQ * D];        // 16 MB
__device__ float g_xg[(size_t)SEQ * G];        // 64 MB
__device__ float g_h1[(size_t)SEQ * D];        // 16 MB
// LL packets: [slot][cta][chunk] = {h0,h1,h2, epoch_bits}
__device__ float4 g_ll[2][NCTA][3];

// ---------------- packed f32x2 helpers (Blackwell) ----------------
#define FMA2(d,a,b,c)  asm("fma.rn.f32x2 %0,%1,%2,%3;" : "=l"(d) : "l"(a), "l"(b), "l"(c))
#define PACK2(d,x)     asm("mov.b64 %0,{%1,%1};"       : "=l"(d) : "f"(x))
#define UNPACK2(lo,hi,v) asm("mov.b64 {%0,%1},%2;"     : "=f"(lo), "=f"(hi) : "l"(v))

__device__ __forceinline__ float sigmoid_fast(float x) {
    return 1.f / (1.f + __expf(-x));
}
__device__ __forceinline__ float tanh_fast(float x) {
    return 2.f / (1.f + __expf(-2.f * x)) - 1.f;
}

// 16B volatile (L2-coherent, single-sector-atomic) load/store — NCCL LL style.
__device__ __forceinline__ float4 ll_load(const float4* p) {
    float4 v;
    asm volatile("ld.volatile.global.v4.f32 {%0,%1,%2,%3}, [%4];"
                 : "=f"(v.x), "=f"(v.y), "=f"(v.z), "=f"(v.w) : "l"(p) : "memory");
    return v;
}
__device__ __forceinline__ void ll_store(float4* p, float4 v) {
    asm volatile("st.volatile.global.v4.f32 [%0], {%1,%2,%3,%4};"
                 :: "l"(p), "f"(v.x), "f"(v.y), "f"(v.z), "f"(v.w) : "memory");
}

// ---------------- init: zero LL packets (epoch=0, h=0) ----------------
__global__ void init_state_kernel() {
    int tid = threadIdx.x;
    float4 z = make_float4(0.f, 0.f, 0.f, 0.f);
    for (int i = tid; i < 2 * NCTA * 3; i += blockDim.x)
        ((float4*)g_ll)[i] = z;
}

// ---------------- SGEMM: C = A@B^T + bias1(+bias2), opt leaky; f32x2 inner ----------------
template<bool RELU>
__global__ __launch_bounds__(256) void sgemm_nt(
    const float* __restrict__ A, const float* __restrict__ B,
    float* __restrict__ C,
    const float* __restrict__ bias1, const float* __restrict__ bias2,
    int M, int N, int K)
{
    __shared__ __align__(16) float As[8][132];
    __shared__ __align__(16) float Bs[8][132];

    const int tid = threadIdx.x;
    const int bm = blockIdx.y, bn = blockIdx.x;
    const int ty = tid >> 4, tx = tid & 15;
    const int lrow = tid >> 1;
    const int lcol = (tid & 1) * 4;

    const float* Aptr = A + (size_t)(bm * 128 + lrow) * K + lcol;
    const float* Bptr = B + (size_t)(bn * 128 + lrow) * K + lcol;

    u64 acc2[8][4];
    #pragma unroll
    for (int i = 0; i < 8; i++)
        #pragma unroll
        for (int j = 0; j < 4; j++) acc2[i][j] = 0ull;

    for (int k0 = 0; k0 < K; k0 += 8) {
        float4 a = *(const float4*)(Aptr + k0);
        float4 b = *(const float4*)(Bptr + k0);
        __syncthreads();
        As[lcol + 0][lrow] = a.x; As[lcol + 1][lrow] = a.y;
        As[lcol + 2][lrow] = a.z; As[lcol + 3][lrow] = a.w;
        Bs[lcol + 0][lrow] = b.x; Bs[lcol + 1][lrow] = b.y;
        Bs[lcol + 2][lrow] = b.z; Bs[lcol + 3][lrow] = b.w;
        __syncthreads();
        #pragma unroll
        for (int k = 0; k < 8; k++) {
            float4 a0 = *(const float4*)&As[k][ty * 8];
            float4 a1 = *(const float4*)&As[k][ty * 8 + 4];
            const ulonglong2* bp = (const ulonglong2*)&Bs[k][tx * 8];
            ulonglong2 q0 = bp[0], q1 = bp[1];
            u64 bv[4] = {q0.x, q0.y, q1.x, q1.y};
            float av[8] = {a0.x,a0.y,a0.z,a0.w,a1.x,a1.y,a1.z,a1.w};
            u64 aa[8];
            #pragma unroll
            for (int i = 0; i < 8; i++) PACK2(aa[i], av[i]);
            #pragma unroll
            for (int i = 0; i < 8; i++)
                #pragma unroll
                for (int j = 0; j < 4; j++)
                    FMA2(acc2[i][j], aa[i], bv[j], acc2[i][j]);
        }
    }

    const int colbase = bn * 128 + tx * 8;
    float bb[8];
    #pragma unroll
    for (int j = 0; j < 8; j++) {
        float v = bias1 ? bias1[colbase + j] : 0.f;
        if (bias2) v += bias2[colbase + j];
        bb[j] = v;
    }
    #pragma unroll
    for (int i = 0; i < 8; i++) {
        int row = bm * 128 + ty * 8 + i;
        float* Crow = C + (size_t)row * N + colbase;
        float o[8];
        #pragma unroll
        for (int j = 0; j < 4; j++) UNPACK2(o[2*j], o[2*j+1], acc2[i][j]);
        #pragma unroll
        for (int j = 0; j < 8; j++) {
            float v = o[j] + bb[j];
            if (RELU) v = v > 0.f ? v : 0.01f * v;
            o[j] = v;
        }
        *(float4*)(Crow)     = make_float4(o[0], o[1], o[2], o[3]);
        *(float4*)(Crow + 4) = make_float4(o[4], o[5], o[6], o[7]);
    }
}

// ---------------- persistent LSTM recurrence (R10 structure, shortened combine) ----------------
// 148 CTAs x 512 thr, 3 __syncthreads/step, shaped 180/60 backoff poll (proven).
// Changes vs R10 (chain-shortening only):
//  (a) warp15 combine: lanes 0-2 each OWN 3 units (c-state per lane, direct gs
//      reads, pack own float4, publish) — no shfl gather chain.
//  (b) matvec tail: lane0 handles r0 and lane16 handles r1 nonlinearity+STS in
//      parallel (butterfly leaves the sum in all lanes).
__global__ __launch_bounds__(RTHR, 1) void lstm_recur_kernel(
    const float* __restrict__ Whh,   // [G][D] this layer
    const float* __restrict__ xg,    // [SEQ][G]
    float* __restrict__ h_hist,
    float* __restrict__ out,
    int store_hist, int store_out)
{
    __shared__ __align__(16) float hs[D];   // assembled h(t)
    __shared__ float gs[32];                // nonlinearized gate values
    __shared__ float xgs[32];

    const int tid  = threadIdx.x;
    const int lane = tid & 31;
    const int wid  = tid >> 5;
    const int cta  = blockIdx.x;

    const int u_begin = (cta * D) / NCTA;
    const int u_end   = ((cta + 1) * D) / NCTA;
    const int nu      = u_end - u_begin;       // 6 or 7
    const int nrows   = 4 * nu;                // 24 or 28

    // ---- poller mapping (tid < 444): chunk tid = (cta c, sub k) ----
    const bool pact = (tid < NCHUNK);
    int p_ub = 0, p_n = 0;
    const float4* p_src0 = nullptr;
    const float4* p_src1 = nullptr;
    if (pact) {
        int c = tid / 3, k = tid - c * 3;
        int cb = (c * D) / NCTA, ce = ((c + 1) * D) / NCTA;
        p_ub = cb + 3 * k;
        p_n  = ce - p_ub; p_n = p_n > 3 ? 3 : p_n;   // may be <=0 -> inactive
        p_src0 = &g_ll[0][c][k];
        p_src1 = &g_ll[1][c][k];
    }
    const bool p_on = pact && (p_n > 0);

    // ---- xg prefetch threads (warp 14, tids 448+) ----
    const bool ldr = (tid >= 448) && (tid - 448 < nrows);
    int my_grow = 0; float xr = 0.f;
    if (ldr) {
        int r = tid - 448;
        int gate = r / nu, ui = r - gate * nu;
        my_grow = gate * D + u_begin + ui;
        xr = __ldg(&xg[my_grow]);              // prefetch t=0
    }

    // ---- matvec warps 0-13: rows r0=2w, r1=2w+1, weights in registers ----
    const int r0 = wid * 2, r1 = r0 + 1;
    const bool act = (wid < 14) && (r0 < nrows);
    int gate0 = 0, gate1 = 0;                  // gate index of each row
    ulonglong2 wr0[8], wr1[8];
    if (act) {
        gate0 = r0 / nu; gate1 = r1 / nu;
        int grow0 = gate0 * D + u_begin + (r0 - gate0 * nu);
        int grow1 = gate1 * D + u_begin + (r1 - gate1 * nu);
        const ulonglong2* W0 = (const ulonglong2*)(Whh + (size_t)grow0 * D);
        const ulonglong2* W1 = (const ulonglong2*)(Whh + (size_t)grow1 * D);
        #pragma unroll
        for (int j = 0; j < 8; j++) {
            wr0[j] = W0[j * 32 + lane];
            wr1[j] = W1[j * 32 + lane];
        }
    }

    // ---- warp 15: lanes 0-2 each own up to 3 units (c-state in registers) ----
    const bool gw = (wid == 15);
    float c0 = 0.f, c1 = 0.f, c2 = 0.f;
    int o_ub = 0, o_n = 0;                     // owned unit range (local idx)
    float4* pub0 = nullptr; float4* pub1 = nullptr;
    if (gw && lane < 3) {
        o_ub = 3 * lane;
        o_n  = nu - o_ub; o_n = o_n > 3 ? 3 : (o_n < 0 ? 0 : o_n);
        pub0 = &g_ll[0][cta][lane]; pub1 = &g_ll[1][cta][lane];
    }
    const bool own = gw && (lane < 3) && (o_n > 0);
    __syncthreads();

    for (int t = 0; t < SEQ; t++) {
        // ---- phase 1: ingest h(t) via LL packets (shaped poll) / stage xg(t) ----
        if (p_on) {
            const float4* src = (t & 1) ? p_src1 : p_src0;
            const unsigned want = (unsigned)t;
            float4 v = ll_load(src);                 // immediate: free if ready
            if (__float_as_uint(v.w) != want) {
                __nanosleep(180);                    // skip the dead window
                v = ll_load(src);
                while (__float_as_uint(v.w) != want) {
                    __nanosleep(60);                 // tight tail
                    v = ll_load(src);
                }
            }
            hs[p_ub] = v.x;
            if (p_n > 1) hs[p_ub + 1] = v.y;
            if (p_n > 2) hs[p_ub + 2] = v.z;
        } else if (ldr) {
            xgs[tid - 448] = xr;
            if (t + 1 < SEQ) xr = __ldg(&xg[(size_t)(t + 1) * G + my_grow]);
        }
        __syncthreads();

        // ---- phase 2: matvec + warp reduce + nonlinearity at source ----
        if (act) {
            u64 a0 = 0ull, a1 = 0ull, b0 = 0ull, b1 = 0ull;
            #pragma unroll
            for (int j = 0; j < 8; j++) {
                ulonglong2 hv = ((const ulonglong2*)hs)[j * 32 + lane];
                FMA2(a0, wr0[j].x, hv.x, a0);
                FMA2(a1, wr0[j].y, hv.y, a1);
                FMA2(b0, wr1[j].x, hv.x, b0);
                FMA2(b1, wr1[j].y, hv.y, b1);
            }
            float a0l, a0h, a1l, a1h, b0l, b0h, b1l, b1h;
            UNPACK2(a0l, a0h, a0); UNPACK2(a1l, a1h, a1);
            UNPACK2(b0l, b0h, b0); UNPACK2(b1l, b1h, b1);
            float acc0 = (a0l + a0h) + (a1l + a1h);
            float acc1 = (b0l + b0h) + (b1l + b1h);
            #pragma unroll
            for (int off = 16; off; off >>= 1) {
                acc0 += __shfl_xor_sync(0xffffffffu, acc0, off);
                acc1 += __shfl_xor_sync(0xffffffffu, acc1, off);
            }
            if (lane == 0) {                      // r0 on lane 0
                float v0 = acc0 + xgs[r0];
                gs[r0] = (gate0 == 2) ? tanh_fast(v0) : sigmoid_fast(v0);
            } else if (lane == 16) {              // r1 on lane 16, in parallel
                float v1 = acc1 + xgs[r1];
                gs[r1] = (gate1 == 2) ? tanh_fast(v1) : sigmoid_fast(v1);
            }
        }
        __syncthreads();

        // ---- phase 3: per-lane combine + publish-first (warp 15, lanes 0-2) ----
        if (own) {
            float h0 = 0.f, h1 = 0.f, h2 = 0.f;
            {
                int u = o_ub;
                float gi = gs[0 * nu + u], gf = gs[1 * nu + u];
                float gg = gs[2 * nu + u], go = gs[3 * nu + u];
                c0 = gf * c0 + gi * gg;
                h0 = go * tanh_fast(c0);
            }
            if (o_n > 1) {
                int u = o_ub + 1;
                float gi = gs[0 * nu + u], gf = gs[1 * nu + u];
                float gg = gs[2 * nu + u], go = gs[3 * nu + u];
                c1 = gf * c1 + gi * gg;
                h1 = go * tanh_fast(c1);
            }
            if (o_n > 2) {
                int u = o_ub + 2;
                float gi = gs[0 * nu + u], gf = gs[1 * nu + u];
                float gg = gs[2 * nu + u], go = gs[3 * nu + u];
                c2 = gf * c2 + gi * gg;
                h2 = go * tanh_fast(c2);
            }
            if (t + 1 < SEQ) {
                float4 pkt = make_float4(h0, h1, h2, __uint_as_float((unsigned)(t + 1)));
                ll_store(((t + 1) & 1) ? pub1 : pub0, pkt);
            }
            if (store_hist) {
                float* hh = h_hist + (size_t)t * D + u_begin + o_ub;
                hh[0] = h0;
                if (o_n > 1) hh[1] = h1;
                if (o_n > 2) hh[2] = h2;
            }
            if (store_out && t == SEQ - 1) {
                float* op = out + u_begin + o_ub;
                op[0] = h0 > 0.f ? h0 : 0.01f * h0;
                if (o_n > 1) op[1] = h1 > 0.f ? h1 : 0.01f * h1;
                if (o_n > 2) op[2] = h2 > 0.f ? h2 : 0.01f * h2;
            }
        }
        __syncthreads();   // protect hs/xgs/gs for next iteration
    }
}

// ---------------- launch ----------------
extern "C" void kernel_launch(void* const* d_in, const int* in_sizes, int n_in,
                              void* d_out, int out_size)
{
    const float* inp = (const float*)d_in[0];   // (4096, 64)
    const float* W1  = (const float*)d_in[1];   // (1024, 64)
    const float* b1  = (const float*)d_in[2];   // (1024,)
    const float* Wih = (const float*)d_in[3];   // (2, 4096, 1024)
    const float* Whh = (const float*)d_in[4];   // (2, 4096, 1024)
    const float* bih = (const float*)d_in[5];   // (2, 4096)
    const float* bhh = (const float*)d_in[6];   // (2, 4096)
    float* out = (float*)d_out;                 // (1,1,1024)

    float *gx, *gxg, *gh1;
    cudaGetSymbolAddress((void**)&gx,  g_x);
    cudaGetSymbolAddress((void**)&gxg, g_xg);
    cudaGetSymbolAddress((void**)&gh1, g_h1);

    // Phase A: x = leaky_relu(inp @ W1^T + b1)
    sgemm_nt<true><<<dim3(D / 128, SEQ / 128), 256>>>(
        inp, W1, gx, b1, nullptr, SEQ, D, INDIM);

    // Phase B: xg1 = x @ Wih1^T + (bih1 + bhh1)
    sgemm_nt<false><<<dim3(G / 128, SEQ / 128), 256>>>(
        gx, Wih, gxg, bih, bhh, SEQ, G, D);

    // Layer-1 recurrence (writes g_h1)
    init_state_kernel<<<1, 1024>>>();
    lstm_recur_kernel<<<NCTA, RTHR>>>(Whh, gxg, gh1, out, 1, 0);

    // Phase C: xg2 = h1 @ Wih2^T + (bih2 + bhh2)
    sgemm_nt<false><<<dim3(G / 128, SEQ / 128), 256>>>(
        gh1, Wih + (size_t)G * D, gxg, bih + G, bhh + G, SEQ, G, D);

    // Layer-2 recurrence (writes final leaky_relu(h_T) to out)
    init_state_kernel<<<1, 1024>>>();
    lstm_recur_kernel<<<NCTA, RTHR>>>(Whh + (size_t)G * D, gxg, gh1, out, 0, 1);
}

// round 13
// speedup vs baseline: 1.2323x; 1.2323x over previous
#include <cuda_runtime.h>
#include <math.h>
#include <stdint.h>

#define SEQ   4096
#define INDIM 64
#define D     1024
#define G     4096      // 4*D
#define NCTA  148
#define RTHR  512
#define NCHUNK (NCTA * 3)   // 444 LL packets (3 per CTA, some partial/inactive)

typedef unsigned long long u64;

// ---------------- scratch (device globals: allocation-free) ----------------
__device__ float g_x [(size_t)SEQ * D];        // 16 MB
__device__ float g_xg[(size_t)SEQ * G];        // 64 MB
__device__ float g_h1[(size_t)SEQ * D];        // 16 MB
// LL packets: [slot][cta][chunk] = {h0,h1,h2, epoch_bits}
__device__ float4 g_ll[2][NCTA][3];

// ---------------- packed f32x2 helpers (Blackwell) ----------------
#define FMA2(d,a,b,c)  asm("fma.rn.f32x2 %0,%1,%2,%3;" : "=l"(d) : "l"(a), "l"(b), "l"(c))
#define PACK2(d,x)     asm("mov.b64 %0,{%1,%1};"       : "=l"(d) : "f"(x))
#define UNPACK2(lo,hi,v) asm("mov.b64 {%0,%1},%2;"     : "=f"(lo), "=f"(hi) : "l"(v))

__device__ __forceinline__ float sigmoid_fast(float x) {
    return 1.f / (1.f + __expf(-x));
}
__device__ __forceinline__ float tanh_fast(float x) {
    return 2.f / (1.f + __expf(-2.f * x)) - 1.f;
}

// 16B volatile (L2-coherent, single-sector-atomic) load/store — NCCL LL style.
__device__ __forceinline__ float4 ll_load(const float4* p) {
    float4 v;
    asm volatile("ld.volatile.global.v4.f32 {%0,%1,%2,%3}, [%4];"
                 : "=f"(v.x), "=f"(v.y), "=f"(v.z), "=f"(v.w) : "l"(p) : "memory");
    return v;
}
__device__ __forceinline__ void ll_store(float4* p, float4 v) {
    asm volatile("st.volatile.global.v4.f32 [%0], {%1,%2,%3,%4};"
                 :: "l"(p), "f"(v.x), "f"(v.y), "f"(v.z), "f"(v.w) : "memory");
}

// ---------------- init: zero LL packets (epoch=0, h=0) ----------------
__global__ void init_state_kernel() {
    int tid = threadIdx.x;
    float4 z = make_float4(0.f, 0.f, 0.f, 0.f);
    for (int i = tid; i < 2 * NCTA * 3; i += blockDim.x)
        ((float4*)g_ll)[i] = z;
}

// ---------------- SGEMM: C = A@B^T + bias1(+bias2), opt leaky; f32x2 inner ----------------
// BM=BN=128, BK=8, 256 threads, 8x8/thread. Software prefetch: next K-tile's
// LDG is issued right after the barrier, then hidden under the 256-FMA2 block.
template<bool RELU>
__global__ __launch_bounds__(256) void sgemm_nt(
    const float* __restrict__ A, const float* __restrict__ B,
    float* __restrict__ C,
    const float* __restrict__ bias1, const float* __restrict__ bias2,
    int M, int N, int K)
{
    __shared__ __align__(16) float As[8][132];
    __shared__ __align__(16) float Bs[8][132];

    const int tid = threadIdx.x;
    const int bm = blockIdx.y, bn = blockIdx.x;
    const int ty = tid >> 4, tx = tid & 15;
    const int lrow = tid >> 1;
    const int lcol = (tid & 1) * 4;

    const float* Aptr = A + (size_t)(bm * 128 + lrow) * K + lcol;
    const float* Bptr = B + (size_t)(bn * 128 + lrow) * K + lcol;

    u64 acc2[8][4];
    #pragma unroll
    for (int i = 0; i < 8; i++)
        #pragma unroll
        for (int j = 0; j < 4; j++) acc2[i][j] = 0ull;

    // prologue: fetch tile 0
    float4 a = *(const float4*)(Aptr);
    float4 b = *(const float4*)(Bptr);

    for (int k0 = 0; k0 < K; k0 += 8) {
        __syncthreads();
        As[lcol + 0][lrow] = a.x; As[lcol + 1][lrow] = a.y;
        As[lcol + 2][lrow] = a.z; As[lcol + 3][lrow] = a.w;
        Bs[lcol + 0][lrow] = b.x; Bs[lcol + 1][lrow] = b.y;
        Bs[lcol + 2][lrow] = b.z; Bs[lcol + 3][lrow] = b.w;
        __syncthreads();
        // issue next tile's loads NOW; latency hidden under the FMA block
        if (k0 + 8 < K) {
            a = *(const float4*)(Aptr + k0 + 8);
            b = *(const float4*)(Bptr + k0 + 8);
        }
        #pragma unroll
        for (int k = 0; k < 8; k++) {
            float4 a0 = *(const float4*)&As[k][ty * 8];
            float4 a1 = *(const float4*)&As[k][ty * 8 + 4];
            const ulonglong2* bp = (const ulonglong2*)&Bs[k][tx * 8];
            ulonglong2 q0 = bp[0], q1 = bp[1];
            u64 bv[4] = {q0.x, q0.y, q1.x, q1.y};
            float av[8] = {a0.x,a0.y,a0.z,a0.w,a1.x,a1.y,a1.z,a1.w};
            u64 aa[8];
            #pragma unroll
            for (int i = 0; i < 8; i++) PACK2(aa[i], av[i]);
            #pragma unroll
            for (int i = 0; i < 8; i++)
                #pragma unroll
                for (int j = 0; j < 4; j++)
                    FMA2(acc2[i][j], aa[i], bv[j], acc2[i][j]);
        }
    }

    const int colbase = bn * 128 + tx * 8;
    float bb[8];
    #pragma unroll
    for (int j = 0; j < 8; j++) {
        float v = bias1 ? bias1[colbase + j] : 0.f;
        if (bias2) v += bias2[colbase + j];
        bb[j] = v;
    }
    #pragma unroll
    for (int i = 0; i < 8; i++) {
        int row = bm * 128 + ty * 8 + i;
        float* Crow = C + (size_t)row * N + colbase;
        float o[8];
        #pragma unroll
        for (int j = 0; j < 4; j++) UNPACK2(o[2*j], o[2*j+1], acc2[i][j]);
        #pragma unroll
        for (int j = 0; j < 8; j++) {
            float v = o[j] + bb[j];
            if (RELU) v = v > 0.f ? v : 0.01f * v;
            o[j] = v;
        }
        *(float4*)(Crow)     = make_float4(o[0], o[1], o[2], o[3]);
        *(float4*)(Crow + 4) = make_float4(o[4], o[5], o[6], o[7]);
    }
}

// ---------------- persistent LSTM recurrence (R10 EXACT — frozen local optimum) ----------------
// 148 CTAs x 512 thr, 3 __syncthreads/step, shaped 180/60 backoff poll,
// nonlinearity at matvec source, warp 15 combine (7 lanes parallel) + publish-first.
__global__ __launch_bounds__(RTHR, 1) void lstm_recur_kernel(
    const float* __restrict__ Whh,   // [G][D] this layer
    const float* __restrict__ xg,    // [SEQ][G]
    float* __restrict__ h_hist,
    float* __restrict__ out,
    int store_hist, int store_out)
{
    __shared__ __align__(16) float hs[D];   // assembled h(t)
    __shared__ float gs[32];                // nonlinearized gate values
    __shared__ float xgs[32];

    const int tid  = threadIdx.x;
    const int lane = tid & 31;
    const int wid  = tid >> 5;
    const int cta  = blockIdx.x;

    const int u_begin = (cta * D) / NCTA;
    const int u_end   = ((cta + 1) * D) / NCTA;
    const int nu      = u_end - u_begin;       // 6 or 7
    const int nrows   = 4 * nu;                // 24 or 28

    // ---- poller mapping (tid < 444): chunk tid = (cta c, sub k) ----
    const bool pact = (tid < NCHUNK);
    int p_ub = 0, p_n = 0;
    const float4* p_src0 = nullptr;
    const float4* p_src1 = nullptr;
    if (pact) {
        int c = tid / 3, k = tid - c * 3;
        int cb = (c * D) / NCTA, ce = ((c + 1) * D) / NCTA;
        p_ub = cb + 3 * k;
        p_n  = ce - p_ub; p_n = p_n > 3 ? 3 : p_n;   // may be <=0 -> inactive
        p_src0 = &g_ll[0][c][k];
        p_src1 = &g_ll[1][c][k];
    }
    const bool p_on = pact && (p_n > 0);

    // ---- xg prefetch threads (warp 14, tids 448+) ----
    const bool ldr = (tid >= 448) && (tid - 448 < nrows);
    int my_grow = 0; float xr = 0.f;
    if (ldr) {
        int r = tid - 448;
        int gate = r / nu, ui = r - gate * nu;
        my_grow = gate * D + u_begin + ui;
        xr = __ldg(&xg[my_grow]);              // prefetch t=0
    }

    // ---- matvec warps 0-13: rows r0=2w, r1=2w+1, weights in registers ----
    const int r0 = wid * 2, r1 = r0 + 1;
    const bool act = (wid < 14) && (r0 < nrows);
    int gate0 = 0, gate1 = 0;                  // gate index of each row
    ulonglong2 wr0[8], wr1[8];
    if (act) {
        gate0 = r0 / nu; gate1 = r1 / nu;
        int grow0 = gate0 * D + u_begin + (r0 - gate0 * nu);
        int grow1 = gate1 * D + u_begin + (r1 - gate1 * nu);
        const ulonglong2* W0 = (const ulonglong2*)(Whh + (size_t)grow0 * D);
        const ulonglong2* W1 = (const ulonglong2*)(Whh + (size_t)grow1 * D);
        #pragma unroll
        for (int j = 0; j < 8; j++) {
            wr0[j] = W0[j * 32 + lane];
            wr1[j] = W1[j * 32 + lane];
        }
    }

    // ---- warp 15: per-unit combine + publish ----
    const bool gw = (wid == 15);
    const bool u_on = lane < nu;
    float c_reg = 0.f;
    float4* pub0 = nullptr; float4* pub1 = nullptr;
    bool pub_on = false;
    if (gw) {
        pub_on = (lane < 3) && (3 * lane < nu);
        if (lane < 3) { pub0 = &g_ll[0][cta][lane]; pub1 = &g_ll[1][cta][lane]; }
    }
    __syncthreads();

    for (int t = 0; t < SEQ; t++) {
        // ---- phase 1: ingest h(t) via LL packets (reshaped poll) / stage xg(t) ----
        if (p_on) {
            const float4* src = (t & 1) ? p_src1 : p_src0;
            const unsigned want = (unsigned)t;
            float4 v = ll_load(src);                 // immediate: free if ready
            if (__float_as_uint(v.w) != want) {
                __nanosleep(180);                    // skip the dead window
                v = ll_load(src);
                while (__float_as_uint(v.w) != want) {
                    __nanosleep(60);                 // tight tail
                    v = ll_load(src);
                }
            }
            hs[p_ub] = v.x;
            if (p_n > 1) hs[p_ub + 1] = v.y;
            if (p_n > 2) hs[p_ub + 2] = v.z;
        } else if (ldr) {
            xgs[tid - 448] = xr;
            if (t + 1 < SEQ) xr = __ldg(&xg[(size_t)(t + 1) * G + my_grow]);
        }
        __syncthreads();

        // ---- phase 2: matvec + warp reduce + nonlinearity at source ----
        if (act) {
            u64 a0 = 0ull, a1 = 0ull, b0 = 0ull, b1 = 0ull;
            #pragma unroll
            for (int j = 0; j < 8; j++) {
                ulonglong2 hv = ((const ulonglong2*)hs)[j * 32 + lane];
                FMA2(a0, wr0[j].x, hv.x, a0);
                FMA2(a1, wr0[j].y, hv.y, a1);
                FMA2(b0, wr1[j].x, hv.x, b0);
                FMA2(b1, wr1[j].y, hv.y, b1);
            }
            float a0l, a0h, a1l, a1h, b0l, b0h, b1l, b1h;
            UNPACK2(a0l, a0h, a0); UNPACK2(a1l, a1h, a1);
            UNPACK2(b0l, b0h, b0); UNPACK2(b1l, b1h, b1);
            float acc0 = (a0l + a0h) + (a1l + a1h);
            float acc1 = (b0l + b0h) + (b1l + b1h);
            #pragma unroll
            for (int off = 16; off; off >>= 1) {
                acc0 += __shfl_xor_sync(0xffffffffu, acc0, off);
                acc1 += __shfl_xor_sync(0xffffffffu, acc1, off);
            }
            if (lane == 0) {
                float v0 = acc0 + xgs[r0];
                float v1 = acc1 + xgs[r1];
                gs[r0] = (gate0 == 2) ? tanh_fast(v0) : sigmoid_fast(v0);
                gs[r1] = (gate1 == 2) ? tanh_fast(v1) : sigmoid_fast(v1);
            }
        }
        __syncthreads();

        // ---- phase 3: combine + publish-first (warp 15 only) ----
        if (gw) {
            float h = 0.f;
            if (u_on) {
                float gi = gs[0 * nu + lane];
                float gf = gs[1 * nu + lane];
                float gg = gs[2 * nu + lane];
                float go = gs[3 * nu + lane];
                c_reg = gf * c_reg + gi * gg;
                h = go * tanh_fast(c_reg);
            }
            float h0 = __shfl_sync(0xffffffffu, h, 3 * lane + 0);
            float h1 = __shfl_sync(0xffffffffu, h, 3 * lane + 1);
            float h2 = __shfl_sync(0xffffffffu, h, 3 * lane + 2);
            if (pub_on && t + 1 < SEQ) {
                float4 pkt = make_float4(h0, h1, h2, __uint_as_float((unsigned)(t + 1)));
                ll_store(((t + 1) & 1) ? pub1 : pub0, pkt);
            }
            if (u_on) {
                if (store_hist) h_hist[(size_t)t * D + u_begin + lane] = h;
                if (store_out && t == SEQ - 1)
                    out[u_begin + lane] = h > 0.f ? h : 0.01f * h;
            }
        }
        __syncthreads();   // protect hs/xgs/gs for next iteration
    }
}

// ---------------- launch ----------------
extern "C" void kernel_launch(void* const* d_in, const int* in_sizes, int n_in,
                              void* d_out, int out_size)
{
    const float* inp = (const float*)d_in[0];   // (4096, 64)
    const float* W1  = (const float*)d_in[1];   // (1024, 64)
    const float* b1  = (const float*)d_in[2];   // (1024,)
    const float* Wih = (const float*)d_in[3];   // (2, 4096, 1024)
    const float* Whh = (const float*)d_in[4];   // (2, 4096, 1024)
    const float* bih = (const float*)d_in[5];   // (2, 4096)
    const float* bhh = (const float*)d_in[6];   // (2, 4096)
    float* out = (float*)d_out;                 // (1,1,1024)

    float *gx, *gxg, *gh1;
    cudaGetSymbolAddress((void**)&gx,  g_x);
    cudaGetSymbolAddress((void**)&gxg, g_xg);
    cudaGetSymbolAddress((void**)&gh1, g_h1);

    // Phase A: x = leaky_relu(inp @ W1^T + b1)
    sgemm_nt<true><<<dim3(D / 128, SEQ / 128), 256>>>(
        inp, W1, gx, b1, nullptr, SEQ, D, INDIM);

    // Phase B: xg1 = x @ Wih1^T + (bih1 + bhh1)
    sgemm_nt<false><<<dim3(G / 128, SEQ / 128), 256>>>(
        gx, Wih, gxg, bih, bhh, SEQ, G, D);

    // Layer-1 recurrence (writes g_h1)
    init_state_kernel<<<1, 1024>>>();
    lstm_recur_kernel<<<NCTA, RTHR>>>(Whh, gxg, gh1, out, 1, 0);

    // Phase C: xg2 = h1 @ Wih2^T + (bih2 + bhh2)
    sgemm_nt<false><<<dim3(G / 128, SEQ / 128), 256>>>(
        gh1, Wih + (size_t)G * D, gxg, bih + G, bhh + G, SEQ, G, D);

    // Layer-2 recurrence (writes final leaky_relu(h_T) to out)
    init_state_kernel<<<1, 1024>>>();
    lstm_recur_kernel<<<NCTA, RTHR>>>(Whh + (size_t)G * D, gxg, gh1, out, 0, 1);
}

// round 14
// speedup vs baseline: 1.3355x; 1.0837x over previous
#include <cuda_runtime.h>
#include <math.h>
#include <stdint.h>

#define SEQ   4096
#define INDIM 64
#define D     1024
#define G     4096      // 4*D
#define NCTA  148
#define RTHR  512
#define NCHUNK (NCTA * 3)   // 444 LL packets (3 per CTA, some partial/inactive)

typedef unsigned long long u64;

// ---------------- scratch (device globals: allocation-free) ----------------
__device__ float g_x [(size_t)SEQ * D];        // 16 MB
__device__ float g_xg[(size_t)SEQ * G];        // 64 MB
__device__ float g_h1[(size_t)SEQ * D];        // 16 MB
// LL packets: [slot][cta][chunk] = {h0,h1,h2, epoch_bits}
__device__ float4 g_ll[2][NCTA][3];

// ---------------- packed f32x2 helpers (Blackwell) ----------------
#define FMA2(d,a,b,c)  asm("fma.rn.f32x2 %0,%1,%2,%3;" : "=l"(d) : "l"(a), "l"(b), "l"(c))
#define PACK2(d,x)     asm("mov.b64 %0,{%1,%1};"       : "=l"(d) : "f"(x))
#define UNPACK2(lo,hi,v) asm("mov.b64 {%0,%1},%2;"     : "=f"(lo), "=f"(hi) : "l"(v))

__device__ __forceinline__ float sigmoid_fast(float x) {
    return 1.f / (1.f + __expf(-x));
}
__device__ __forceinline__ float tanh_fast(float x) {
    return 2.f / (1.f + __expf(-2.f * x)) - 1.f;
}

// Precise ALU-timed delays: dependent IADD chain, 4 cyc/add, no wakeup
// quantization (replaces __nanosleep whose granularity is unspecified).
__device__ __forceinline__ void alu_delay75() {   // ~300 cyc ≈ 150 ns @2GHz
    unsigned x = threadIdx.x;
    #pragma unroll
    for (int i = 0; i < 75; i++)
        asm volatile("add.u32 %0, %0, 1;" : "+r"(x));
}
__device__ __forceinline__ void alu_delay25() {   // ~100 cyc ≈ 50 ns @2GHz
    unsigned x = threadIdx.x;
    #pragma unroll
    for (int i = 0; i < 25; i++)
        asm volatile("add.u32 %0, %0, 1;" : "+r"(x));
}

// 16B volatile (L2-coherent, single-sector-atomic) load/store — NCCL LL style.
__device__ __forceinline__ float4 ll_load(const float4* p) {
    float4 v;
    asm volatile("ld.volatile.global.v4.f32 {%0,%1,%2,%3}, [%4];"
                 : "=f"(v.x), "=f"(v.y), "=f"(v.z), "=f"(v.w) : "l"(p) : "memory");
    return v;
}
__device__ __forceinline__ void ll_store(float4* p, float4 v) {
    asm volatile("st.volatile.global.v4.f32 [%0], {%1,%2,%3,%4};"
                 :: "l"(p), "f"(v.x), "f"(v.y), "f"(v.z), "f"(v.w) : "memory");
}

// ---------------- init: zero LL packets (epoch=0, h=0) ----------------
__global__ void init_state_kernel() {
    int tid = threadIdx.x;
    float4 z = make_float4(0.f, 0.f, 0.f, 0.f);
    for (int i = tid; i < 2 * NCTA * 3; i += blockDim.x)
        ((float4*)g_ll)[i] = z;
}

// ---------------- SGEMM: C = A@B^T + bias1(+bias2), opt leaky; f32x2 inner ----------------
// BM=BN=128, BK=8, 256 threads, 8x8/thread, software prefetch (R13).
template<bool RELU>
__global__ __launch_bounds__(256) void sgemm_nt(
    const float* __restrict__ A, const float* __restrict__ B,
    float* __restrict__ C,
    const float* __restrict__ bias1, const float* __restrict__ bias2,
    int M, int N, int K)
{
    __shared__ __align__(16) float As[8][132];
    __shared__ __align__(16) float Bs[8][132];

    const int tid = threadIdx.x;
    const int bm = blockIdx.y, bn = blockIdx.x;
    const int ty = tid >> 4, tx = tid & 15;
    const int lrow = tid >> 1;
    const int lcol = (tid & 1) * 4;

    const float* Aptr = A + (size_t)(bm * 128 + lrow) * K + lcol;
    const float* Bptr = B + (size_t)(bn * 128 + lrow) * K + lcol;

    u64 acc2[8][4];
    #pragma unroll
    for (int i = 0; i < 8; i++)
        #pragma unroll
        for (int j = 0; j < 4; j++) acc2[i][j] = 0ull;

    float4 a = *(const float4*)(Aptr);
    float4 b = *(const float4*)(Bptr);

    for (int k0 = 0; k0 < K; k0 += 8) {
        __syncthreads();
        As[lcol + 0][lrow] = a.x; As[lcol + 1][lrow] = a.y;
        As[lcol + 2][lrow] = a.z; As[lcol + 3][lrow] = a.w;
        Bs[lcol + 0][lrow] = b.x; Bs[lcol + 1][lrow] = b.y;
        Bs[lcol + 2][lrow] = b.z; Bs[lcol + 3][lrow] = b.w;
        __syncthreads();
        if (k0 + 8 < K) {
            a = *(const float4*)(Aptr + k0 + 8);
            b = *(const float4*)(Bptr + k0 + 8);
        }
        #pragma unroll
        for (int k = 0; k < 8; k++) {
            float4 a0 = *(const float4*)&As[k][ty * 8];
            float4 a1 = *(const float4*)&As[k][ty * 8 + 4];
            const ulonglong2* bp = (const ulonglong2*)&Bs[k][tx * 8];
            ulonglong2 q0 = bp[0], q1 = bp[1];
            u64 bv[4] = {q0.x, q0.y, q1.x, q1.y};
            float av[8] = {a0.x,a0.y,a0.z,a0.w,a1.x,a1.y,a1.z,a1.w};
            u64 aa[8];
            #pragma unroll
            for (int i = 0; i < 8; i++) PACK2(aa[i], av[i]);
            #pragma unroll
            for (int i = 0; i < 8; i++)
                #pragma unroll
                for (int j = 0; j < 4; j++)
                    FMA2(acc2[i][j], aa[i], bv[j], acc2[i][j]);
        }
    }

    const int colbase = bn * 128 + tx * 8;
    float bb[8];
    #pragma unroll
    for (int j = 0; j < 8; j++) {
        float v = bias1 ? bias1[colbase + j] : 0.f;
        if (bias2) v += bias2[colbase + j];
        bb[j] = v;
    }
    #pragma unroll
    for (int i = 0; i < 8; i++) {
        int row = bm * 128 + ty * 8 + i;
        float* Crow = C + (size_t)row * N + colbase;
        float o[8];
        #pragma unroll
        for (int j = 0; j < 4; j++) UNPACK2(o[2*j], o[2*j+1], acc2[i][j]);
        #pragma unroll
        for (int j = 0; j < 8; j++) {
            float v = o[j] + bb[j];
            if (RELU) v = v > 0.f ? v : 0.01f * v;
            o[j] = v;
        }
        *(float4*)(Crow)     = make_float4(o[0], o[1], o[2], o[3]);
        *(float4*)(Crow + 4) = make_float4(o[4], o[5], o[6], o[7]);
    }
}

// ---------------- persistent LSTM recurrence (R10 structure; ALU-timed poll) ----------------
// 148 CTAs x 512 thr, 3 __syncthreads/step. ONLY change vs R10: the backoff
// poll uses precise dependent-ALU delays (75 adds ≈150ns, 25 adds ≈50ns)
// instead of __nanosleep, eliminating sleep-quantum overshoot.
__global__ __launch_bounds__(RTHR, 1) void lstm_recur_kernel(
    const float* __restrict__ Whh,   // [G][D] this layer
    const float* __restrict__ xg,    // [SEQ][G]
    float* __restrict__ h_hist,
    float* __restrict__ out,
    int store_hist, int store_out)
{
    __shared__ __align__(16) float hs[D];   // assembled h(t)
    __shared__ float gs[32];                // nonlinearized gate values
    __shared__ float xgs[32];

    const int tid  = threadIdx.x;
    const int lane = tid & 31;
    const int wid  = tid >> 5;
    const int cta  = blockIdx.x;

    const int u_begin = (cta * D) / NCTA;
    const int u_end   = ((cta + 1) * D) / NCTA;
    const int nu      = u_end - u_begin;       // 6 or 7
    const int nrows   = 4 * nu;                // 24 or 28

    // ---- poller mapping (tid < 444): chunk tid = (cta c, sub k) ----
    const bool pact = (tid < NCHUNK);
    int p_ub = 0, p_n = 0;
    const float4* p_src0 = nullptr;
    const float4* p_src1 = nullptr;
    if (pact) {
        int c = tid / 3, k = tid - c * 3;
        int cb = (c * D) / NCTA, ce = ((c + 1) * D) / NCTA;
        p_ub = cb + 3 * k;
        p_n  = ce - p_ub; p_n = p_n > 3 ? 3 : p_n;   // may be <=0 -> inactive
        p_src0 = &g_ll[0][c][k];
        p_src1 = &g_ll[1][c][k];
    }
    const bool p_on = pact && (p_n > 0);

    // ---- xg prefetch threads (warp 14, tids 448+) ----
    const bool ldr = (tid >= 448) && (tid - 448 < nrows);
    int my_grow = 0; float xr = 0.f;
    if (ldr) {
        int r = tid - 448;
        int gate = r / nu, ui = r - gate * nu;
        my_grow = gate * D + u_begin + ui;
        xr = __ldg(&xg[my_grow]);              // prefetch t=0
    }

    // ---- matvec warps 0-13: rows r0=2w, r1=2w+1, weights in registers ----
    const int r0 = wid * 2, r1 = r0 + 1;
    const bool act = (wid < 14) && (r0 < nrows);
    int gate0 = 0, gate1 = 0;                  // gate index of each row
    ulonglong2 wr0[8], wr1[8];
    if (act) {
        gate0 = r0 / nu; gate1 = r1 / nu;
        int grow0 = gate0 * D + u_begin + (r0 - gate0 * nu);
        int grow1 = gate1 * D + u_begin + (r1 - gate1 * nu);
        const ulonglong2* W0 = (const ulonglong2*)(Whh + (size_t)grow0 * D);
        const ulonglong2* W1 = (const ulonglong2*)(Whh + (size_t)grow1 * D);
        #pragma unroll
        for (int j = 0; j < 8; j++) {
            wr0[j] = W0[j * 32 + lane];
            wr1[j] = W1[j * 32 + lane];
        }
    }

    // ---- warp 15: per-unit combine + publish ----
    const bool gw = (wid == 15);
    const bool u_on = lane < nu;
    float c_reg = 0.f;
    float4* pub0 = nullptr; float4* pub1 = nullptr;
    bool pub_on = false;
    if (gw) {
        pub_on = (lane < 3) && (3 * lane < nu);
        if (lane < 3) { pub0 = &g_ll[0][cta][lane]; pub1 = &g_ll[1][cta][lane]; }
    }
    __syncthreads();

    for (int t = 0; t < SEQ; t++) {
        // ---- phase 1: ingest h(t) via LL packets (ALU-timed poll) / stage xg(t) ----
        if (p_on) {
            const float4* src = (t & 1) ? p_src1 : p_src0;
            const unsigned want = (unsigned)t;
            float4 v = ll_load(src);                 // immediate: free if ready
            if (__float_as_uint(v.w) != want) {
                alu_delay75();                       // skip the dead window (~150ns)
                v = ll_load(src);
                while (__float_as_uint(v.w) != want) {
                    alu_delay25();                   // tight tail (~50ns + RTT)
                    v = ll_load(src);
                }
            }
            hs[p_ub] = v.x;
            if (p_n > 1) hs[p_ub + 1] = v.y;
            if (p_n > 2) hs[p_ub + 2] = v.z;
        } else if (ldr) {
            xgs[tid - 448] = xr;
            if (t + 1 < SEQ) xr = __ldg(&xg[(size_t)(t + 1) * G + my_grow]);
        }
        __syncthreads();

        // ---- phase 2: matvec + warp reduce + nonlinearity at source ----
        if (act) {
            u64 a0 = 0ull, a1 = 0ull, b0 = 0ull, b1 = 0ull;
            #pragma unroll
            for (int j = 0; j < 8; j++) {
                ulonglong2 hv = ((const ulonglong2*)hs)[j * 32 + lane];
                FMA2(a0, wr0[j].x, hv.x, a0);
                FMA2(a1, wr0[j].y, hv.y, a1);
                FMA2(b0, wr1[j].x, hv.x, b0);
                FMA2(b1, wr1[j].y, hv.y, b1);
            }
            float a0l, a0h, a1l, a1h, b0l, b0h, b1l, b1h;
            UNPACK2(a0l, a0h, a0); UNPACK2(a1l, a1h, a1);
            UNPACK2(b0l, b0h, b0); UNPACK2(b1l, b1h, b1);
            float acc0 = (a0l + a0h) + (a1l + a1h);
            float acc1 = (b0l + b0h) + (b1l + b1h);
            #pragma unroll
            for (int off = 16; off; off >>= 1) {
                acc0 += __shfl_xor_sync(0xffffffffu, acc0, off);
                acc1 += __shfl_xor_sync(0xffffffffu, acc1, off);
            }
            if (lane == 0) {
                float v0 = acc0 + xgs[r0];
                float v1 = acc1 + xgs[r1];
                gs[r0] = (gate0 == 2) ? tanh_fast(v0) : sigmoid_fast(v0);
                gs[r1] = (gate1 == 2) ? tanh_fast(v1) : sigmoid_fast(v1);
            }
        }
        __syncthreads();

        // ---- phase 3: combine + publish-first (warp 15 only) ----
        if (gw) {
            float h = 0.f;
            if (u_on) {
                float gi = gs[0 * nu + lane];
                float gf = gs[1 * nu + lane];
                float gg = gs[2 * nu + lane];
                float go = gs[3 * nu + lane];
                c_reg = gf * c_reg + gi * gg;
                h = go * tanh_fast(c_reg);
            }
            float h0 = __shfl_sync(0xffffffffu, h, 3 * lane + 0);
            float h1 = __shfl_sync(0xffffffffu, h, 3 * lane + 1);
            float h2 = __shfl_sync(0xffffffffu, h, 3 * lane + 2);
            if (pub_on && t + 1 < SEQ) {
                float4 pkt = make_float4(h0, h1, h2, __uint_as_float((unsigned)(t + 1)));
                ll_store(((t + 1) & 1) ? pub1 : pub0, pkt);
            }
            if (u_on) {
                if (store_hist) h_hist[(size_t)t * D + u_begin + lane] = h;
                if (store_out && t == SEQ - 1)
                    out[u_begin + lane] = h > 0.f ? h : 0.01f * h;
            }
        }
        __syncthreads();   // protect hs/xgs/gs for next iteration
    }
}

// ---------------- launch ----------------
extern "C" void kernel_launch(void* const* d_in, const int* in_sizes, int n_in,
                              void* d_out, int out_size)
{
    const float* inp = (const float*)d_in[0];   // (4096, 64)
    const float* W1  = (const float*)d_in[1];   // (1024, 64)
    const float* b1  = (const float*)d_in[2];   // (1024,)
    const float* Wih = (const float*)d_in[3];   // (2, 4096, 1024)
    const float* Whh = (const float*)d_in[4];   // (2, 4096, 1024)
    const float* bih = (const float*)d_in[5];   // (2, 4096)
    const float* bhh = (const float*)d_in[6];   // (2, 4096)
    float* out = (float*)d_out;                 // (1,1,1024)

    float *gx, *gxg, *gh1;
    cudaGetSymbolAddress((void**)&gx,  g_x);
    cudaGetSymbolAddress((void**)&gxg, g_xg);
    cudaGetSymbolAddress((void**)&gh1, g_h1);

    // Phase A: x = leaky_relu(inp @ W1^T + b1)
    sgemm_nt<true><<<dim3(D / 128, SEQ / 128), 256>>>(
        inp, W1, gx, b1, nullptr, SEQ, D, INDIM);

    // Phase B: xg1 = x @ Wih1^T + (bih1 + bhh1)
    sgemm_nt<false><<<dim3(G / 128, SEQ / 128), 256>>>(
        gx, Wih, gxg, bih, bhh, SEQ, G, D);

    // Layer-1 recurrence (writes g_h1)
    init_state_kernel<<<1, 1024>>>();
    lstm_recur_kernel<<<NCTA, RTHR>>>(Whh, gxg, gh1, out, 1, 0);

    // Phase C: xg2 = h1 @ Wih2^T + (bih2 + bhh2)
    sgemm_nt<false><<<dim3(G / 128, SEQ / 128), 256>>>(
        gh1, Wih + (size_t)G * D, gxg, bih + G, bhh + G, SEQ, G, D);

    // Layer-2 recurrence (writes final leaky_relu(h_T) to out)
    init_state_kernel<<<1, 1024>>>();
    lstm_recur_kernel<<<NCTA, RTHR>>>(Whh + (size_t)G * D, gxg, gh1, out, 0, 1);
}

// round 15
// speedup vs baseline: 1.3394x; 1.0029x over previous
#include <cuda_runtime.h>
#include <math.h>
#include <stdint.h>

#define SEQ   4096
#define INDIM 64
#define D     1024
#define G     4096      // 4*D
#define NCTA  148
#define RTHR  512
#define NCHUNK (NCTA * 3)   // 444 LL packets (3 per CTA, some partial/inactive)

typedef unsigned long long u64;

// ---------------- scratch (device globals: allocation-free) ----------------
__device__ float g_x [(size_t)SEQ * D];        // 16 MB
__device__ float g_xg[(size_t)SEQ * G];        // 64 MB
__device__ float g_h1[(size_t)SEQ * D];        // 16 MB
// LL packets: [slot][cta][chunk] = {h0,h1,h2, epoch_bits}
__device__ float4 g_ll[2][NCTA][3];

// ---------------- packed f32x2 helpers (Blackwell) ----------------
#define FMA2(d,a,b,c)  asm("fma.rn.f32x2 %0,%1,%2,%3;" : "=l"(d) : "l"(a), "l"(b), "l"(c))
#define PACK2(d,x)     asm("mov.b64 %0,{%1,%1};"       : "=l"(d) : "f"(x))
#define UNPACK2(lo,hi,v) asm("mov.b64 {%0,%1},%2;"     : "=f"(lo), "=f"(hi) : "l"(v))

__device__ __forceinline__ float sigmoid_fast(float x) {
    return 1.f / (1.f + __expf(-x));
}
__device__ __forceinline__ float tanh_fast(float x) {
    return 2.f / (1.f + __expf(-2.f * x)) - 1.f;
}

// Precise ALU-timed delays: dependent IADD chain, 4 cyc/add, no wakeup
// quantization. R15: tightened schedule (40 adds ~160cyc head, 12 adds ~48cyc
// tail) — poll traffic stays well under the ~6.3KB/cyc LTS cap.
__device__ __forceinline__ void alu_delay_head() {   // ~160 cyc
    unsigned x = threadIdx.x;
    #pragma unroll
    for (int i = 0; i < 40; i++)
        asm volatile("add.u32 %0, %0, 1;" : "+r"(x));
}
__device__ __forceinline__ void alu_delay_tail() {   // ~48 cyc
    unsigned x = threadIdx.x;
    #pragma unroll
    for (int i = 0; i < 12; i++)
        asm volatile("add.u32 %0, %0, 1;" : "+r"(x));
}

// 16B volatile (L2-coherent, single-sector-atomic) load/store — NCCL LL style.
__device__ __forceinline__ float4 ll_load(const float4* p) {
    float4 v;
    asm volatile("ld.volatile.global.v4.f32 {%0,%1,%2,%3}, [%4];"
                 : "=f"(v.x), "=f"(v.y), "=f"(v.z), "=f"(v.w) : "l"(p) : "memory");
    return v;
}
__device__ __forceinline__ void ll_store(float4* p, float4 v) {
    asm volatile("st.volatile.global.v4.f32 [%0], {%1,%2,%3,%4};"
                 :: "l"(p), "f"(v.x), "f"(v.y), "f"(v.z), "f"(v.w) : "memory");
}

// ---------------- init: zero LL packets (epoch=0, h=0) ----------------
__global__ void init_state_kernel() {
    int tid = threadIdx.x;
    float4 z = make_float4(0.f, 0.f, 0.f, 0.f);
    for (int i = tid; i < 2 * NCTA * 3; i += blockDim.x)
        ((float4*)g_ll)[i] = z;
}

// ---------------- SGEMM: C = A@B^T + bias1(+bias2), opt leaky; f32x2 inner ----------------
// BM=BN=128, BK=8, 256 threads, 8x8/thread, software prefetch (R13).
template<bool RELU>
__global__ __launch_bounds__(256) void sgemm_nt(
    const float* __restrict__ A, const float* __restrict__ B,
    float* __restrict__ C,
    const float* __restrict__ bias1, const float* __restrict__ bias2,
    int M, int N, int K)
{
    __shared__ __align__(16) float As[8][132];
    __shared__ __align__(16) float Bs[8][132];

    const int tid = threadIdx.x;
    const int bm = blockIdx.y, bn = blockIdx.x;
    const int ty = tid >> 4, tx = tid & 15;
    const int lrow = tid >> 1;
    const int lcol = (tid & 1) * 4;

    const float* Aptr = A + (size_t)(bm * 128 + lrow) * K + lcol;
    const float* Bptr = B + (size_t)(bn * 128 + lrow) * K + lcol;

    u64 acc2[8][4];
    #pragma unroll
    for (int i = 0; i < 8; i++)
        #pragma unroll
        for (int j = 0; j < 4; j++) acc2[i][j] = 0ull;

    float4 a = *(const float4*)(Aptr);
    float4 b = *(const float4*)(Bptr);

    for (int k0 = 0; k0 < K; k0 += 8) {
        __syncthreads();
        As[lcol + 0][lrow] = a.x; As[lcol + 1][lrow] = a.y;
        As[lcol + 2][lrow] = a.z; As[lcol + 3][lrow] = a.w;
        Bs[lcol + 0][lrow] = b.x; Bs[lcol + 1][lrow] = b.y;
        Bs[lcol + 2][lrow] = b.z; Bs[lcol + 3][lrow] = b.w;
        __syncthreads();
        if (k0 + 8 < K) {
            a = *(const float4*)(Aptr + k0 + 8);
            b = *(const float4*)(Bptr + k0 + 8);
        }
        #pragma unroll
        for (int k = 0; k < 8; k++) {
            float4 a0 = *(const float4*)&As[k][ty * 8];
            float4 a1 = *(const float4*)&As[k][ty * 8 + 4];
            const ulonglong2* bp = (const ulonglong2*)&Bs[k][tx * 8];
            ulonglong2 q0 = bp[0], q1 = bp[1];
            u64 bv[4] = {q0.x, q0.y, q1.x, q1.y};
            float av[8] = {a0.x,a0.y,a0.z,a0.w,a1.x,a1.y,a1.z,a1.w};
            u64 aa[8];
            #pragma unroll
            for (int i = 0; i < 8; i++) PACK2(aa[i], av[i]);
            #pragma unroll
            for (int i = 0; i < 8; i++)
                #pragma unroll
                for (int j = 0; j < 4; j++)
                    FMA2(acc2[i][j], aa[i], bv[j], acc2[i][j]);
        }
    }

    const int colbase = bn * 128 + tx * 8;
    float bb[8];
    #pragma unroll
    for (int j = 0; j < 8; j++) {
        float v = bias1 ? bias1[colbase + j] : 0.f;
        if (bias2) v += bias2[colbase + j];
        bb[j] = v;
    }
    #pragma unroll
    for (int i = 0; i < 8; i++) {
        int row = bm * 128 + ty * 8 + i;
        float* Crow = C + (size_t)row * N + colbase;
        float o[8];
        #pragma unroll
        for (int j = 0; j < 4; j++) UNPACK2(o[2*j], o[2*j+1], acc2[i][j]);
        #pragma unroll
        for (int j = 0; j < 8; j++) {
            float v = o[j] + bb[j];
            if (RELU) v = v > 0.f ? v : 0.01f * v;
            o[j] = v;
        }
        *(float4*)(Crow)     = make_float4(o[0], o[1], o[2], o[3]);
        *(float4*)(Crow + 4) = make_float4(o[4], o[5], o[6], o[7]);
    }
}

// ---------------- persistent LSTM recurrence (R14 structure; tightened delays) ----------------
// 148 CTAs x 512 thr, 3 __syncthreads/step, ALU-timed backoff poll.
// ONLY change vs R14: head delay 75->40 adds, tail delay 25->12 adds.
__global__ __launch_bounds__(RTHR, 1) void lstm_recur_kernel(
    const float* __restrict__ Whh,   // [G][D] this layer
    const float* __restrict__ xg,    // [SEQ][G]
    float* __restrict__ h_hist,
    float* __restrict__ out,
    int store_hist, int store_out)
{
    __shared__ __align__(16) float hs[D];   // assembled h(t)
    __shared__ float gs[32];                // nonlinearized gate values
    __shared__ float xgs[32];

    const int tid  = threadIdx.x;
    const int lane = tid & 31;
    const int wid  = tid >> 5;
    const int cta  = blockIdx.x;

    const int u_begin = (cta * D) / NCTA;
    const int u_end   = ((cta + 1) * D) / NCTA;
    const int nu      = u_end - u_begin;       // 6 or 7
    const int nrows   = 4 * nu;                // 24 or 28

    // ---- poller mapping (tid < 444): chunk tid = (cta c, sub k) ----
    const bool pact = (tid < NCHUNK);
    int p_ub = 0, p_n = 0;
    const float4* p_src0 = nullptr;
    const float4* p_src1 = nullptr;
    if (pact) {
        int c = tid / 3, k = tid - c * 3;
        int cb = (c * D) / NCTA, ce = ((c + 1) * D) / NCTA;
        p_ub = cb + 3 * k;
        p_n  = ce - p_ub; p_n = p_n > 3 ? 3 : p_n;   // may be <=0 -> inactive
        p_src0 = &g_ll[0][c][k];
        p_src1 = &g_ll[1][c][k];
    }
    const bool p_on = pact && (p_n > 0);

    // ---- xg prefetch threads (warp 14, tids 448+) ----
    const bool ldr = (tid >= 448) && (tid - 448 < nrows);
    int my_grow = 0; float xr = 0.f;
    if (ldr) {
        int r = tid - 448;
        int gate = r / nu, ui = r - gate * nu;
        my_grow = gate * D + u_begin + ui;
        xr = __ldg(&xg[my_grow]);              // prefetch t=0
    }

    // ---- matvec warps 0-13: rows r0=2w, r1=2w+1, weights in registers ----
    const int r0 = wid * 2, r1 = r0 + 1;
    const bool act = (wid < 14) && (r0 < nrows);
    int gate0 = 0, gate1 = 0;                  // gate index of each row
    ulonglong2 wr0[8], wr1[8];
    if (act) {
        gate0 = r0 / nu; gate1 = r1 / nu;
        int grow0 = gate0 * D + u_begin + (r0 - gate0 * nu);
        int grow1 = gate1 * D + u_begin + (r1 - gate1 * nu);
        const ulonglong2* W0 = (const ulonglong2*)(Whh + (size_t)grow0 * D);
        const ulonglong2* W1 = (const ulonglong2*)(Whh + (size_t)grow1 * D);
        #pragma unroll
        for (int j = 0; j < 8; j++) {
            wr0[j] = W0[j * 32 + lane];
            wr1[j] = W1[j * 32 + lane];
        }
    }

    // ---- warp 15: per-unit combine + publish ----
    const bool gw = (wid == 15);
    const bool u_on = lane < nu;
    float c_reg = 0.f;
    float4* pub0 = nullptr; float4* pub1 = nullptr;
    bool pub_on = false;
    if (gw) {
        pub_on = (lane < 3) && (3 * lane < nu);
        if (lane < 3) { pub0 = &g_ll[0][cta][lane]; pub1 = &g_ll[1][cta][lane]; }
    }
    __syncthreads();

    for (int t = 0; t < SEQ; t++) {
        // ---- phase 1: ingest h(t) via LL packets (ALU-timed poll) / stage xg(t) ----
        if (p_on) {
            const float4* src = (t & 1) ? p_src1 : p_src0;
            const unsigned want = (unsigned)t;
            float4 v = ll_load(src);                 // immediate: free if ready
            if (__float_as_uint(v.w) != want) {
                alu_delay_head();                    // ~160 cyc
                v = ll_load(src);
                while (__float_as_uint(v.w) != want) {
                    alu_delay_tail();                // ~48 cyc + RTT period
                    v = ll_load(src);
                }
            }
            hs[p_ub] = v.x;
            if (p_n > 1) hs[p_ub + 1] = v.y;
            if (p_n > 2) hs[p_ub + 2] = v.z;
        } else if (ldr) {
            xgs[tid - 448] = xr;
            if (t + 1 < SEQ) xr = __ldg(&xg[(size_t)(t + 1) * G + my_grow]);
        }
        __syncthreads();

        // ---- phase 2: matvec + warp reduce + nonlinearity at source ----
        if (act) {
            u64 a0 = 0ull, a1 = 0ull, b0 = 0ull, b1 = 0ull;
            #pragma unroll
            for (int j = 0; j < 8; j++) {
                ulonglong2 hv = ((const ulonglong2*)hs)[j * 32 + lane];
                FMA2(a0, wr0[j].x, hv.x, a0);
                FMA2(a1, wr0[j].y, hv.y, a1);
                FMA2(b0, wr1[j].x, hv.x, b0);
                FMA2(b1, wr1[j].y, hv.y, b1);
            }
            float a0l, a0h, a1l, a1h, b0l, b0h, b1l, b1h;
            UNPACK2(a0l, a0h, a0); UNPACK2(a1l, a1h, a1);
            UNPACK2(b0l, b0h, b0); UNPACK2(b1l, b1h, b1);
            float acc0 = (a0l + a0h) + (a1l + a1h);
            float acc1 = (b0l + b0h) + (b1l + b1h);
            #pragma unroll
            for (int off = 16; off; off >>= 1) {
                acc0 += __shfl_xor_sync(0xffffffffu, acc0, off);
                acc1 += __shfl_xor_sync(0xffffffffu, acc1, off);
            }
            if (lane == 0) {
                float v0 = acc0 + xgs[r0];
                float v1 = acc1 + xgs[r1];
                gs[r0] = (gate0 == 2) ? tanh_fast(v0) : sigmoid_fast(v0);
                gs[r1] = (gate1 == 2) ? tanh_fast(v1) : sigmoid_fast(v1);
            }
        }
        __syncthreads();

        // ---- phase 3: combine + publish-first (warp 15 only) ----
        if (gw) {
            float h = 0.f;
            if (u_on) {
                float gi = gs[0 * nu + lane];
                float gf = gs[1 * nu + lane];
                float gg = gs[2 * nu + lane];
                float go = gs[3 * nu + lane];
                c_reg = gf * c_reg + gi * gg;
                h = go * tanh_fast(c_reg);
            }
            float h0 = __shfl_sync(0xffffffffu, h, 3 * lane + 0);
            float h1 = __shfl_sync(0xffffffffu, h, 3 * lane + 1);
            float h2 = __shfl_sync(0xffffffffu, h, 3 * lane + 2);
            if (pub_on && t + 1 < SEQ) {
                float4 pkt = make_float4(h0, h1, h2, __uint_as_float((unsigned)(t + 1)));
                ll_store(((t + 1) & 1) ? pub1 : pub0, pkt);
            }
            if (u_on) {
                if (store_hist) h_hist[(size_t)t * D + u_begin + lane] = h;
                if (store_out && t == SEQ - 1)
                    out[u_begin + lane] = h > 0.f ? h : 0.01f * h;
            }
        }
        __syncthreads();   // protect hs/xgs/gs for next iteration
    }
}

// ---------------- launch ----------------
extern "C" void kernel_launch(void* const* d_in, const int* in_sizes, int n_in,
                              void* d_out, int out_size)
{
    const float* inp = (const float*)d_in[0];   // (4096, 64)
    const float* W1  = (const float*)d_in[1];   // (1024, 64)
    const float* b1  = (const float*)d_in[2];   // (1024,)
    const float* Wih = (const float*)d_in[3];   // (2, 4096, 1024)
    const float* Whh = (const float*)d_in[4];   // (2, 4096, 1024)
    const float* bih = (const float*)d_in[5];   // (2, 4096)
    const float* bhh = (const float*)d_in[6];   // (2, 4096)
    float* out = (float*)d_out;                 // (1,1,1024)

    float *gx, *gxg, *gh1;
    cudaGetSymbolAddress((void**)&gx,  g_x);
    cudaGetSymbolAddress((void**)&gxg, g_xg);
    cudaGetSymbolAddress((void**)&gh1, g_h1);

    // Phase A: x = leaky_relu(inp @ W1^T + b1)
    sgemm_nt<true><<<dim3(D / 128, SEQ / 128), 256>>>(
        inp, W1, gx, b1, nullptr, SEQ, D, INDIM);

    // Phase B: xg1 = x @ Wih1^T + (bih1 + bhh1)
    sgemm_nt<false><<<dim3(G / 128, SEQ / 128), 256>>>(
        gx, Wih, gxg, bih, bhh, SEQ, G, D);

    // Layer-1 recurrence (writes g_h1)
    init_state_kernel<<<1, 1024>>>();
    lstm_recur_kernel<<<NCTA, RTHR>>>(Whh, gxg, gh1, out, 1, 0);

    // Phase C: xg2 = h1 @ Wih2^T + (bih2 + bhh2)
    sgemm_nt<false><<<dim3(G / 128, SEQ / 128), 256>>>(
        gh1, Wih + (size_t)G * D, gxg, bih + G, bhh + G, SEQ, G, D);

    // Layer-2 recurrence (writes final leaky_relu(h_T) to out)
    init_state_kernel<<<1, 1024>>>();
    lstm_recur_kernel<<<NCTA, RTHR>>>(Whh + (size_t)G * D, gxg, gh1, out, 0, 1);
}